// round 2
// baseline (speedup 1.0000x reference)
#include <cuda_runtime.h>
#include <math.h>

#define FULLMASK 0xffffffffu
#define CB 2
#define CH 32
#define CHKV 8
#define CR 4
#define CD 128
#define CDIM 4096
#define CSTART 32768
#define CPREF 28672
#define CNPG 1792
#define CPAGE 16
#define CTOP 256
#define CSCALE 0.08838834764831845f

#define SCHUNKS 56   // scoring chunks per (b,hkv): 32 pages each
#define PCH 32       // prefix chunks per (b,hkv): 32 union entries each
#define SCH 32       // suffix chunks per (b,hkv): 128 keys each
#define NPART 512    // per head: 256 prefix warp-partials + 256 suffix
#define PSTR 132     // floats per partial: m, l, pad, pad, acc[128]

// ---------------- scratch (device globals; no allocation allowed) ------------
__device__ float g_q[CB * CH * CD];
__device__ float g_kn[CB * CHKV * CD];
__device__ float g_vn[CB * CHKV * CD];
__device__ float g_sc[CB * CNPG * CHKV * CR];        // [b][page][hkv][r]
__device__ int   g_top[CB * CHKV * CR * CTOP];
__device__ int   g_uni[CB * CHKV * 1024];            // page | mask<<16
__device__ int   g_ucnt[CB * CHKV];
__device__ float g_part[(size_t)CB * CH * NPART * PSTR];
__device__ float g_attn[CB * CDIM];

__device__ __forceinline__ float dot4(float4 a, float4 b) {
    return a.x * b.x + a.y * b.y + a.z * b.z + a.w * b.w;
}

// ---------------- 1) QKV GEMV (both batches share each weight row) -----------
__global__ void qkv_kernel(const float* __restrict__ x, const float* __restrict__ wq,
                           const float* __restrict__ wk, const float* __restrict__ wv) {
    __shared__ float sx0[CDIM], sx1[CDIM];
    for (int i = threadIdx.x; i < CDIM; i += 256) { sx0[i] = x[i]; sx1[i] = x[CDIM + i]; }
    __syncthreads();
    int warp = threadIdx.x >> 5, lane = threadIdx.x & 31;
    int row0 = (blockIdx.x * 8 + warp) * 4;
    for (int rr = 0; rr < 4; rr++) {
        int row = row0 + rr;           // 0..6143: [wq 4096 | wk 1024 | wv 1024]
        const float* w;
        if (row < 4096)      w = wq + (size_t)row * CDIM;
        else if (row < 5120) w = wk + (size_t)(row - 4096) * CDIM;
        else                 w = wv + (size_t)(row - 5120) * CDIM;
        float a0 = 0.f, a1 = 0.f;
        for (int j = lane * 4; j < CDIM; j += 128) {
            float4 wv4 = *(const float4*)(w + j);
            float4 x0 = *(const float4*)(sx0 + j);
            float4 x1 = *(const float4*)(sx1 + j);
            a0 += dot4(wv4, x0);
            a1 += dot4(wv4, x1);
        }
        for (int o = 16; o; o >>= 1) {
            a0 += __shfl_xor_sync(FULLMASK, a0, o);
            a1 += __shfl_xor_sync(FULLMASK, a1, o);
        }
        if (lane == 0) {
            if (row < 4096)      { g_q[row] = a0;  g_q[CDIM + row] = a1; }
            else if (row < 5120) { int i = row - 4096; g_kn[i] = a0; g_kn[CHKV * CD + i] = a1; }
            else                 { int i = row - 5120; g_vn[i] = a0; g_vn[CHKV * CD + i] = a1; }
        }
    }
}

// ---------------- 2) RoPE on q and new k (interleaved pairs) -----------------
__global__ void rope_kernel(const float* __restrict__ fc, const float* __restrict__ fs) {
    int idx = blockIdx.x * 256 + threadIdx.x;
    if (idx >= CB * (CH + CHKV) * (CD / 2)) return;
    int i = idx & 63;
    int rem = idx >> 6;               // b*(H+HKV) + hh
    int b = rem / (CH + CHKV);
    int hh = rem % (CH + CHKV);
    float c = fc[i], s = fs[i];
    float* base = (hh < CH) ? (g_q + (b * CH + hh) * CD)
                            : (g_kn + (b * CHKV + (hh - CH)) * CD);
    float t0 = base[2 * i], t1 = base[2 * i + 1];
    base[2 * i]     = t0 * c - t1 * s;
    base[2 * i + 1] = t0 * s + t1 * c;
}

// ---------------- 3) page scoring: max over page of dot(k, q_r) --------------
// 4-value warp butterfly: lane ends holding sum for r = lane&3 (replicated x8)
__global__ void score_kernel(const float* __restrict__ ck) {
    int bid = blockIdx.x;
    int chunk = bid % SCHUNKS;
    int bh = bid / SCHUNKS;
    int hkv = bh % CHKV, b = bh / CHKV;
    int warp = threadIdx.x >> 5, lane = threadIdx.x & 31;
    const float* qb = g_q + (b * CH + hkv * CR) * CD + lane * 4;
    float4 q0 = *(const float4*)(qb);
    float4 q1 = *(const float4*)(qb + CD);
    float4 q2 = *(const float4*)(qb + 2 * CD);
    float4 q3 = *(const float4*)(qb + 3 * CD);
    bool h1 = lane & 1, h2 = lane & 2;
    int page0 = chunk * 32 + warp * 4;
    for (int pp = 0; pp < 4; pp++) {
        int page = page0 + pp;
        const float* kp = ck + (((size_t)b * CSTART + (size_t)page * CPAGE) * CHKV + hkv) * CD + lane * 4;
        float mx = -1e30f;
        for (int g = 0; g < 4; g++) {
            float4 kk[4];
#pragma unroll
            for (int t = 0; t < 4; t++) kk[t] = *(const float4*)(kp + (size_t)(g * 4 + t) * (CHKV * CD));
#pragma unroll
            for (int t = 0; t < 4; t++) {
                float v0 = dot4(kk[t], q0), v1 = dot4(kk[t], q1);
                float v2 = dot4(kk[t], q2), v3 = dot4(kk[t], q3);
                float a01 = h1 ? v1 : v0, b01 = h1 ? v0 : v1;
                a01 += __shfl_xor_sync(FULLMASK, b01, 1);
                float a23 = h1 ? v3 : v2, b23 = h1 ? v2 : v3;
                a23 += __shfl_xor_sync(FULLMASK, b23, 1);
                float aa = h2 ? a23 : a01, bb = h2 ? a01 : a23;
                aa += __shfl_xor_sync(FULLMASK, bb, 2);
                aa += __shfl_xor_sync(FULLMASK, aa, 4);
                aa += __shfl_xor_sync(FULLMASK, aa, 8);
                aa += __shfl_xor_sync(FULLMASK, aa, 16);
                mx = fmaxf(mx, aa);
            }
        }
        if (lane < 4)
            g_sc[((b * CNPG + page) * CHKV + hkv) * CR + lane] = mx;
    }
}

// ---------------- 4) top-256 pages per (b,hkv,r): bitonic sort ---------------
__global__ void topk_kernel() {
    __shared__ unsigned long long sk[2048];
    int inst = blockIdx.x;                    // b*32 + hkv*4 + r
    int r = inst & 3, hkv = (inst >> 2) & 7, b = inst >> 5;
    for (int i = threadIdx.x; i < 2048; i += 256) {
        unsigned long long key;
        if (i < CNPG) {
            float f = g_sc[((b * CNPG + i) * CHKV + hkv) * CR + r];
            unsigned u = __float_as_uint(f);
            unsigned su = (u >> 31) ? ~u : (u | 0x80000000u);  // ascending-orderable
            unsigned du = ~su;                                  // ascending du == descending f
            key = (((unsigned long long)du) << 32) | (unsigned)i;
        } else {
            key = 0xFFFFFFFFFFFFFFFFull;
        }
        sk[i] = key;
    }
    __syncthreads();
    for (int k = 2; k <= 2048; k <<= 1) {
        for (int j = k >> 1; j; j >>= 1) {
            for (int t = threadIdx.x; t < 1024; t += 256) {
                int i = ((t & ~(j - 1)) << 1) | (t & (j - 1));
                int ixj = i | j;
                unsigned long long A = sk[i], Bv = sk[ixj];
                bool desc = (i & k) != 0;
                if ((A > Bv) != desc) { sk[i] = Bv; sk[ixj] = A; }
            }
            __syncthreads();
        }
    }
    for (int i = threadIdx.x; i < CTOP; i += 256)
        g_top[inst * CTOP + i] = (int)(sk[i] & 0xFFFFFFFFu);
}

// ---------------- 5) union of pages across 4 reps + mask, deterministic -----
__global__ void union_kernel() {
    __shared__ int mask[CNPG];
    __shared__ int wtot[8];
    int bh = blockIdx.x;                      // b*HKV + hkv
    int warp = threadIdx.x >> 5, lane = threadIdx.x & 31;
    for (int i = threadIdx.x; i < CNPG; i += 256) mask[i] = 0;
    __syncthreads();
    for (int r = 0; r < CR; r++) {
        int i = threadIdx.x;
        if (i < CTOP) {
            int p = g_top[(bh * CR + r) * CTOP + i];
            atomicOr(&mask[p], 1 << r);
        }
    }
    __syncthreads();
    int base = threadIdx.x * 7;               // 256*7 = 1792
    int cnt = 0;
    for (int j = 0; j < 7; j++) if (mask[base + j]) cnt++;
    int v = cnt;
    for (int o = 1; o < 32; o <<= 1) {
        int u = __shfl_up_sync(FULLMASK, v, o);
        if (lane >= o) v += u;
    }
    if (lane == 31) wtot[warp] = v;
    __syncthreads();
    if (threadIdx.x == 0) {
        int s = 0;
        for (int i = 0; i < 8; i++) { int t = wtot[i]; wtot[i] = s; s += t; }
        g_ucnt[bh] = (s > 1024) ? 1024 : s;
    }
    __syncthreads();
    int off = v - cnt + wtot[warp];
    for (int j = 0; j < 7; j++) {
        int p = base + j;
        int mk = mask[p];
        if (mk && off < 1024) g_uni[bh * 1024 + off++] = p | (mk << 16);
    }
}

// ---------------- flash inner step (shared by prefix/suffix) -----------------
#define OSUPD(MM, LL, AC, SV)                                                        \
    do {                                                                             \
        if ((SV) > (MM)) {                                                           \
            float cr_ = __expf((MM) - (SV));                                         \
            MM = (SV); LL *= cr_;                                                    \
            AC.x *= cr_; AC.y *= cr_; AC.z *= cr_; AC.w *= cr_;                      \
        }                                                                            \
        float e_ = __expf((SV) - (MM));                                              \
        LL += e_;                                                                    \
        AC.x += e_ * vt.x; AC.y += e_ * vt.y; AC.z += e_ * vt.z; AC.w += e_ * vt.w;  \
    } while (0)

struct OState {
    float m0, m1, m2, m3, l0, l1, l2, l3;
    float4 a0, a1, a2, a3;
};

__device__ __forceinline__ void key_step(OState& st, float4 kk, float4 vt,
                                         float4 q0, float4 q1, float4 q2, float4 q3,
                                         int lane, int pm) {
    float v0 = dot4(kk, q0), v1 = dot4(kk, q1), v2 = dot4(kk, q2), v3 = dot4(kk, q3);
    bool h1 = lane & 1, h2 = lane & 2;
    int myr = lane & 3;
    float a01 = h1 ? v1 : v0, b01 = h1 ? v0 : v1;
    a01 += __shfl_xor_sync(FULLMASK, b01, 1);
    float a23 = h1 ? v3 : v2, b23 = h1 ? v2 : v3;
    a23 += __shfl_xor_sync(FULLMASK, b23, 1);
    float aa = h2 ? a23 : a01, bb = h2 ? a01 : a23;
    aa += __shfl_xor_sync(FULLMASK, bb, 2);
    aa += __shfl_xor_sync(FULLMASK, aa, 4);
    aa += __shfl_xor_sync(FULLMASK, aa, 8);
    aa += __shfl_xor_sync(FULLMASK, aa, 16);
    aa *= CSCALE;                              // lane holds s for r = lane&3
    float u1 = __shfl_xor_sync(FULLMASK, aa, 1);
    float u2 = __shfl_xor_sync(FULLMASK, aa, 2);
    float u3 = __shfl_xor_sync(FULLMASK, u1, 2);
    float s0 = (myr == 0) ? aa : (myr == 1) ? u1 : (myr == 2) ? u2 : u3;
    float s1 = (myr == 1) ? aa : (myr == 0) ? u1 : (myr == 3) ? u2 : u3;
    float s2 = (myr == 2) ? aa : (myr == 3) ? u1 : (myr == 0) ? u2 : u3;
    float s3 = (myr == 3) ? aa : (myr == 2) ? u1 : (myr == 1) ? u2 : u3;
    if (pm & 1) OSUPD(st.m0, st.l0, st.a0, s0);
    if (pm & 2) OSUPD(st.m1, st.l1, st.a1, s1);
    if (pm & 4) OSUPD(st.m2, st.l2, st.a2, s2);
    if (pm & 8) OSUPD(st.m3, st.l3, st.a3, s3);
}

__device__ __forceinline__ void write_partial(const OState& st, int b, int hkv, int slot, int lane) {
#pragma unroll
    for (int r = 0; r < 4; r++) {
        float mm = (r == 0) ? st.m0 : (r == 1) ? st.m1 : (r == 2) ? st.m2 : st.m3;
        float ll = (r == 0) ? st.l0 : (r == 1) ? st.l1 : (r == 2) ? st.l2 : st.l3;
        float4 ac = (r == 0) ? st.a0 : (r == 1) ? st.a1 : (r == 2) ? st.a2 : st.a3;
        float* P = g_part + (((size_t)(b * CH + hkv * CR + r)) * NPART + slot) * PSTR;
        if (lane == 0) { P[0] = mm; P[1] = ll; }
        *(float4*)(P + 4 + lane * 4) = ac;
    }
}

// ---------------- 6) prefix attention over union pages -----------------------
__global__ void prefix_kernel(const float* __restrict__ ck, const float* __restrict__ cv) {
    int bid = blockIdx.x;
    int chunk = bid % PCH;
    int bh = bid / PCH;
    int hkv = bh % CHKV, b = bh / CHKV;
    int warp = threadIdx.x >> 5, lane = threadIdx.x & 31;
    int cnt = g_ucnt[bh];
    const float* qb = g_q + (b * CH + hkv * CR) * CD + lane * 4;
    float4 q0 = *(const float4*)(qb);
    float4 q1 = *(const float4*)(qb + CD);
    float4 q2 = *(const float4*)(qb + 2 * CD);
    float4 q3 = *(const float4*)(qb + 3 * CD);
    OState st;
    st.m0 = st.m1 = st.m2 = st.m3 = -1e30f;
    st.l0 = st.l1 = st.l2 = st.l3 = 0.f;
    st.a0 = st.a1 = st.a2 = st.a3 = make_float4(0.f, 0.f, 0.f, 0.f);
    int e0 = chunk * 32 + warp * 4;
    for (int ei = e0; ei < e0 + 4 && ei < cnt; ei++) {
        int ent = g_uni[bh * 1024 + ei];
        int page = ent & 0xFFFF;
        int pm = ent >> 16;
        size_t boff = (((size_t)b * CSTART + (size_t)page * CPAGE) * CHKV + hkv) * CD + lane * 4;
        const float* kp = ck + boff;
        const float* vp = cv + boff;
        for (int g = 0; g < 4; g++) {
            float4 kk[4], vv[4];
#pragma unroll
            for (int t = 0; t < 4; t++) {
                kk[t] = *(const float4*)(kp + (size_t)(g * 4 + t) * (CHKV * CD));
                vv[t] = *(const float4*)(vp + (size_t)(g * 4 + t) * (CHKV * CD));
            }
#pragma unroll
            for (int t = 0; t < 4; t++)
                key_step(st, kk[t], vv[t], q0, q1, q2, q3, lane, pm);
        }
    }
    write_partial(st, b, hkv, chunk * 8 + warp, lane);
}

// ---------------- 7) suffix attention (window 4096 + new token) --------------
__global__ void suffix_kernel(const float* __restrict__ ck, const float* __restrict__ cv) {
    int bid = blockIdx.x;
    int chunk = bid % SCH;
    int bh = bid / SCH;
    int hkv = bh % CHKV, b = bh / CHKV;
    int warp = threadIdx.x >> 5, lane = threadIdx.x & 31;
    const float* qb = g_q + (b * CH + hkv * CR) * CD + lane * 4;
    float4 q0 = *(const float4*)(qb);
    float4 q1 = *(const float4*)(qb + CD);
    float4 q2 = *(const float4*)(qb + 2 * CD);
    float4 q3 = *(const float4*)(qb + 3 * CD);
    OState st;
    st.m0 = st.m1 = st.m2 = st.m3 = -1e30f;
    st.l0 = st.l1 = st.l2 = st.l3 = 0.f;
    st.a0 = st.a1 = st.a2 = st.a3 = make_float4(0.f, 0.f, 0.f, 0.f);
    int key0 = chunk * 128 + warp * 16;
    size_t boff = (((size_t)b * CSTART + CPREF + key0) * CHKV + hkv) * CD + lane * 4;
    const float* kp = ck + boff;
    const float* vp = cv + boff;
    for (int g = 0; g < 4; g++) {
        float4 kk[4], vv[4];
#pragma unroll
        for (int t = 0; t < 4; t++) {
            kk[t] = *(const float4*)(kp + (size_t)(g * 4 + t) * (CHKV * CD));
            vv[t] = *(const float4*)(vp + (size_t)(g * 4 + t) * (CHKV * CD));
        }
#pragma unroll
        for (int t = 0; t < 4; t++)
            key_step(st, kk[t], vv[t], q0, q1, q2, q3, lane, 15);
    }
    if (chunk == SCH - 1 && warp == 7) {  // the just-computed token
        float4 kk = *(const float4*)(g_kn + (b * CHKV + hkv) * CD + lane * 4);
        float4 vv = *(const float4*)(g_vn + (b * CHKV + hkv) * CD + lane * 4);
        key_step(st, kk, vv, q0, q1, q2, q3, lane, 15);
    }
    write_partial(st, b, hkv, 256 + chunk * 8 + warp, lane);
}

// ---------------- 8) merge all partials (exact logaddexp combine) ------------
__global__ void combine_kernel() {
    int bh = blockIdx.x;                       // b*H + h
    const float* P = g_part + (size_t)bh * NPART * PSTR;
    __shared__ float red[128];
    __shared__ float coef[NPART];
    int t = threadIdx.x;
    float mloc = -1e30f;
    for (int c = t; c < NPART; c += 128) mloc = fmaxf(mloc, P[(size_t)c * PSTR]);
    red[t] = mloc;
    for (int o = 64; o; o >>= 1) { __syncthreads(); if (t < o) red[t] = fmaxf(red[t], red[t + o]); }
    __syncthreads();
    float M = red[0];
    __syncthreads();
    float lloc = 0.f;
    for (int c = t; c < NPART; c += 128) {
        float w = __expf(P[(size_t)c * PSTR] - M);
        coef[c] = w;
        lloc += w * P[(size_t)c * PSTR + 1];
    }
    red[t] = lloc;
    for (int o = 64; o; o >>= 1) { __syncthreads(); if (t < o) red[t] += red[t + o]; }
    __syncthreads();
    float L = red[0];
    float o = 0.f;
    for (int c = 0; c < NPART; c++) o += coef[c] * P[(size_t)c * PSTR + 4 + t];
    int b = bh >> 5, h = bh & 31;
    g_attn[b * CDIM + h * CD + t] = o / L;
}

// ---------------- 9) output GEMV --------------------------------------------
__global__ void out_kernel(const float* __restrict__ wo, float* __restrict__ out) {
    __shared__ float sa0[CDIM], sa1[CDIM];
    for (int i = threadIdx.x; i < CDIM; i += 256) { sa0[i] = g_attn[i]; sa1[i] = g_attn[CDIM + i]; }
    __syncthreads();
    int warp = threadIdx.x >> 5, lane = threadIdx.x & 31;
    int row0 = (blockIdx.x * 8 + warp) * 4;
    for (int rr = 0; rr < 4; rr++) {
        int row = row0 + rr;
        const float* w = wo + (size_t)row * CDIM;
        float a0 = 0.f, a1 = 0.f;
        for (int j = lane * 4; j < CDIM; j += 128) {
            float4 wv4 = *(const float4*)(w + j);
            float4 x0 = *(const float4*)(sa0 + j);
            float4 x1 = *(const float4*)(sa1 + j);
            a0 += dot4(wv4, x0);
            a1 += dot4(wv4, x1);
        }
        for (int o = 16; o; o >>= 1) {
            a0 += __shfl_xor_sync(FULLMASK, a0, o);
            a1 += __shfl_xor_sync(FULLMASK, a1, o);
        }
        if (lane == 0) { out[row] = a0; out[CDIM + row] = a1; }
    }
}

// ---------------- launch ------------------------------------------------------
extern "C" void kernel_launch(void* const* d_in, const int* in_sizes, int n_in,
                              void* d_out, int out_size) {
    (void)in_sizes; (void)n_in; (void)out_size;
    const float* x    = (const float*)d_in[0];
    const float* fcos = (const float*)d_in[1];
    const float* fsin = (const float*)d_in[2];
    const float* ck   = (const float*)d_in[3];
    const float* cv   = (const float*)d_in[4];
    const float* wq   = (const float*)d_in[5];
    const float* wk   = (const float*)d_in[6];
    const float* wv   = (const float*)d_in[7];
    const float* wo   = (const float*)d_in[8];
    float* out = (float*)d_out;

    qkv_kernel<<<192, 256>>>(x, wq, wk, wv);
    rope_kernel<<<20, 256>>>(fcos, fsin);
    score_kernel<<<CB * CHKV * SCHUNKS, 256>>>(ck);
    topk_kernel<<<CB * CHKV * CR, 256>>>();
    union_kernel<<<CB * CHKV, 256>>>();
    prefix_kernel<<<CB * CHKV * PCH, 256>>>(ck, cv);
    suffix_kernel<<<CB * CHKV * SCH, 256>>>(ck, cv);
    combine_kernel<<<CB * CH, 128>>>();
    out_kernel<<<128, 256>>>(wo, out);
}

// round 4
// speedup vs baseline: 1.0474x; 1.0474x over previous
#include <cuda_runtime.h>
#include <math.h>

#define FULLMASK 0xffffffffu
#define CB 2
#define CH 32
#define CHKV 8
#define CR 4
#define CD 128
#define CDIM 4096
#define CSTART 32768
#define CPREF 28672
#define CNPG 1792
#define CPAGE 16
#define CTOP 256
#define CSCALE 0.08838834764831845f

#define SCHUNKS 56   // scoring chunks per (b,hkv): 32 pages each
#define PCH 32       // prefix chunks per (b,hkv): 32 union entries each
#define SCH 32       // suffix chunks per (b,hkv): 128 keys each
#define NPART 512    // per head: 256 prefix warp-partials + 256 suffix
#define PSTR 132     // floats per partial: m, l, pad, pad, acc[128]

// ---------------- scratch (device globals; no allocation allowed) ------------
__device__ float g_q[CB * CH * CD];
__device__ float g_kn[CB * CHKV * CD];
__device__ float g_vn[CB * CHKV * CD];
__device__ float g_sc[CB * CNPG * CHKV * CR];        // [b][page][hkv][r]
__device__ int   g_top[CB * CHKV * CR * CTOP];
__device__ int   g_uni[CB * CHKV * 1024];            // page | mask<<16
__device__ int   g_ucnt[CB * CHKV];
__device__ float g_part[(size_t)CB * CH * NPART * PSTR];
__device__ float g_attn[CB * CDIM];

__device__ __forceinline__ float dot4(float4 a, float4 b) {
    return a.x * b.x + a.y * b.y + a.z * b.z + a.w * b.w;
}

// ---------------- 1) QKV GEMV (both batches share each weight row) -----------
__global__ void qkv_kernel(const float* __restrict__ x, const float* __restrict__ wq,
                           const float* __restrict__ wk, const float* __restrict__ wv) {
    __shared__ float sx0[CDIM], sx1[CDIM];
    for (int i = threadIdx.x; i < CDIM; i += 256) { sx0[i] = x[i]; sx1[i] = x[CDIM + i]; }
    __syncthreads();
    int warp = threadIdx.x >> 5, lane = threadIdx.x & 31;
    int row0 = (blockIdx.x * 8 + warp) * 4;
    for (int rr = 0; rr < 4; rr++) {
        int row = row0 + rr;           // 0..6143: [wq 4096 | wk 1024 | wv 1024]
        const float* w;
        if (row < 4096)      w = wq + (size_t)row * CDIM;
        else if (row < 5120) w = wk + (size_t)(row - 4096) * CDIM;
        else                 w = wv + (size_t)(row - 5120) * CDIM;
        float a0 = 0.f, a1 = 0.f;
        for (int j = lane * 4; j < CDIM; j += 128) {
            float4 wv4 = *(const float4*)(w + j);
            float4 x0 = *(const float4*)(sx0 + j);
            float4 x1 = *(const float4*)(sx1 + j);
            a0 += dot4(wv4, x0);
            a1 += dot4(wv4, x1);
        }
        for (int o = 16; o; o >>= 1) {
            a0 += __shfl_xor_sync(FULLMASK, a0, o);
            a1 += __shfl_xor_sync(FULLMASK, a1, o);
        }
        if (lane == 0) {
            if (row < 4096)      { g_q[row] = a0;  g_q[CDIM + row] = a1; }
            else if (row < 5120) { int i = row - 4096; g_kn[i] = a0; g_kn[CHKV * CD + i] = a1; }
            else                 { int i = row - 5120; g_vn[i] = a0; g_vn[CHKV * CD + i] = a1; }
        }
    }
}

// ---------------- 2) RoPE on q and new k (interleaved pairs) -----------------
__global__ void rope_kernel(const float* __restrict__ fc, const float* __restrict__ fs) {
    int idx = blockIdx.x * 256 + threadIdx.x;
    if (idx >= CB * (CH + CHKV) * (CD / 2)) return;
    int i = idx & 63;
    int rem = idx >> 6;               // b*(H+HKV) + hh
    int b = rem / (CH + CHKV);
    int hh = rem % (CH + CHKV);
    float c = fc[i], s = fs[i];
    float* base = (hh < CH) ? (g_q + (b * CH + hh) * CD)
                            : (g_kn + (b * CHKV + (hh - CH)) * CD);
    float t0 = base[2 * i], t1 = base[2 * i + 1];
    base[2 * i]     = t0 * c - t1 * s;
    base[2 * i + 1] = t0 * s + t1 * c;
}

// ---------------- 3) page scoring ---------------------------------------------
// Warp layout: half-warp h (lanes h*16..h*16+15) owns r-pair (2h, 2h+1).
// Lane owns 8 dims (sub = lane&15, dims sub*8..sub*8+8). Two-value butterfly
// over the 16 lanes: after shfl 1,2,4,8 lane holds full dot for r = 2h+(lane&1).
__global__ void score_kernel(const float* __restrict__ ck) {
    int bid = blockIdx.x;
    int chunk = bid % SCHUNKS;
    int bh = bid / SCHUNKS;
    int hkv = bh % CHKV, b = bh / CHKV;
    int warp = threadIdx.x >> 5, lane = threadIdx.x & 31;
    int half = lane >> 4, sub = lane & 15;
    bool p = lane & 1;
    const float* qb = g_q + (b * CH + hkv * CR + 2 * half) * CD + sub * 8;
    float4 q0a = *(const float4*)(qb);
    float4 q0b = *(const float4*)(qb + 4);
    float4 q1a = *(const float4*)(qb + CD);
    float4 q1b = *(const float4*)(qb + CD + 4);
    int page0 = chunk * 32 + warp * 4;
    for (int pp = 0; pp < 4; pp++) {
        int page = page0 + pp;
        const float* kp = ck + (((size_t)b * CSTART + (size_t)page * CPAGE) * CHKV + hkv) * CD + sub * 8;
        float mx = -1e30f;
        for (int g = 0; g < 8; g++) {  // 16 keys, 2 per batch
            float4 ka0 = *(const float4*)(kp + (size_t)(2 * g) * (CHKV * CD));
            float4 kb0 = *(const float4*)(kp + (size_t)(2 * g) * (CHKV * CD) + 4);
            float4 ka1 = *(const float4*)(kp + (size_t)(2 * g + 1) * (CHKV * CD));
            float4 kb1 = *(const float4*)(kp + (size_t)(2 * g + 1) * (CHKV * CD) + 4);
#pragma unroll
            for (int t = 0; t < 2; t++) {
                float4 ka = t ? ka1 : ka0, kb = t ? kb1 : kb0;
                float v0 = dot4(ka, q0a) + dot4(kb, q0b);
                float v1 = dot4(ka, q1a) + dot4(kb, q1b);
                float a = p ? v1 : v0, bb = p ? v0 : v1;
                a += __shfl_xor_sync(FULLMASK, bb, 1);
                a += __shfl_xor_sync(FULLMASK, a, 2);
                a += __shfl_xor_sync(FULLMASK, a, 4);
                a += __shfl_xor_sync(FULLMASK, a, 8);
                mx = fmaxf(mx, a);
            }
        }
        if ((lane & 14) == 0) {        // lanes 0,1,16,17 -> r = 2*half + p
            int r = 2 * half + (int)p;
            g_sc[((b * CNPG + page) * CHKV + hkv) * CR + r] = mx;
        }
    }
}

// ---------------- 4) top-256 pages per (b,hkv,r): bitonic, 1024 threads ------
__global__ void topk_kernel() {
    __shared__ unsigned long long sk[2048];
    int inst = blockIdx.x;                    // b*32 + hkv*4 + r
    int r = inst & 3, hkv = (inst >> 2) & 7, b = inst >> 5;
    for (int i = threadIdx.x; i < 2048; i += 1024) {
        unsigned long long key;
        if (i < CNPG) {
            float f = g_sc[((b * CNPG + i) * CHKV + hkv) * CR + r];
            unsigned u = __float_as_uint(f);
            unsigned su = (u >> 31) ? ~u : (u | 0x80000000u);  // ascending-orderable
            unsigned du = ~su;                                  // ascending du == descending f
            key = (((unsigned long long)du) << 32) | (unsigned)i;
        } else {
            key = 0xFFFFFFFFFFFFFFFFull;
        }
        sk[i] = key;
    }
    __syncthreads();
    int t = threadIdx.x;                      // one compare per thread per stage
    for (int k = 2; k <= 2048; k <<= 1) {
        for (int j = k >> 1; j; j >>= 1) {
            int i = ((t & ~(j - 1)) << 1) | (t & (j - 1));
            int ixj = i | j;
            unsigned long long A = sk[i], Bv = sk[ixj];
            bool desc = (i & k) != 0;
            if ((A > Bv) != desc) { sk[i] = Bv; sk[ixj] = A; }
            __syncthreads();
        }
    }
    if (t < CTOP)
        g_top[inst * CTOP + t] = (int)(sk[t] & 0xFFFFFFFFu);
}

// ---------------- 5) union of pages across 4 reps + mask, deterministic -----
__global__ void union_kernel() {
    __shared__ int mask[CNPG];
    __shared__ int wtot[8];
    int bh = blockIdx.x;                      // b*HKV + hkv
    int warp = threadIdx.x >> 5, lane = threadIdx.x & 31;
    for (int i = threadIdx.x; i < CNPG; i += 256) mask[i] = 0;
    __syncthreads();
    for (int r = 0; r < CR; r++) {
        int i = threadIdx.x;
        if (i < CTOP) {
            int p = g_top[(bh * CR + r) * CTOP + i];
            atomicOr(&mask[p], 1 << r);
        }
    }
    __syncthreads();
    int base = threadIdx.x * 7;               // 256*7 = 1792
    int cnt = 0;
    for (int j = 0; j < 7; j++) if (mask[base + j]) cnt++;
    int v = cnt;
    for (int o = 1; o < 32; o <<= 1) {
        int u = __shfl_up_sync(FULLMASK, v, o);
        if (lane >= o) v += u;
    }
    if (lane == 31) wtot[warp] = v;
    __syncthreads();
    if (threadIdx.x == 0) {
        int s = 0;
        for (int i = 0; i < 8; i++) { int t = wtot[i]; wtot[i] = s; s += t; }
        g_ucnt[bh] = (s > 1024) ? 1024 : s;
    }
    __syncthreads();
    int off = v - cnt + wtot[warp];
    for (int j = 0; j < 7; j++) {
        int p = base + j;
        int mk = mask[p];
        if (mk && off < 1024) g_uni[bh * 1024 + off++] = p | (mk << 16);
    }
}

// ---------------- flash inner step (half-warp r-pair layout) -----------------
// Per lane: two softmax states (r = 2h and 2h+1), acc covers this lane's 8 dims.
#define UPD2(MM, LL, ACA, ACB, SV)                                                   \
    do {                                                                             \
        if ((SV) > (MM)) {                                                           \
            float cr_ = __expf((MM) - (SV));                                         \
            MM = (SV); LL *= cr_;                                                    \
            ACA.x *= cr_; ACA.y *= cr_; ACA.z *= cr_; ACA.w *= cr_;                  \
            ACB.x *= cr_; ACB.y *= cr_; ACB.z *= cr_; ACB.w *= cr_;                  \
        }                                                                            \
        float e_ = __expf((SV) - (MM));                                              \
        LL += e_;                                                                    \
        ACA.x += e_ * va.x; ACA.y += e_ * va.y; ACA.z += e_ * va.z; ACA.w += e_ * va.w; \
        ACB.x += e_ * vb.x; ACB.y += e_ * vb.y; ACB.z += e_ * vb.z; ACB.w += e_ * vb.w; \
    } while (0)

struct HState {
    float m0, l0, m1, l1;
    float4 a0a, a0b, a1a, a1b;
};

__device__ __forceinline__ void key_step2(HState& st, float4 ka, float4 kb,
                                          float4 va, float4 vb,
                                          float4 q0a, float4 q0b, float4 q1a, float4 q1b,
                                          bool p, bool en0, bool en1) {
    float v0 = dot4(ka, q0a) + dot4(kb, q0b);
    float v1 = dot4(ka, q1a) + dot4(kb, q1b);
    float a = p ? v1 : v0, bb = p ? v0 : v1;
    a += __shfl_xor_sync(FULLMASK, bb, 1);
    a += __shfl_xor_sync(FULLMASK, a, 2);
    a += __shfl_xor_sync(FULLMASK, a, 4);
    a += __shfl_xor_sync(FULLMASK, a, 8);
    a *= CSCALE;                               // lane holds s for r = 2h+(lane&1)
    float so = __shfl_xor_sync(FULLMASK, a, 1);
    float sA = p ? so : a;                     // r = 2h
    float sB = p ? a : so;                     // r = 2h+1
    if (en0) UPD2(st.m0, st.l0, st.a0a, st.a0b, sA);
    if (en1) UPD2(st.m1, st.l1, st.a1a, st.a1b, sB);
}

__device__ __forceinline__ void write_partial2(const HState& st, int b, int hkv,
                                               int half, int sub, int slot) {
    int rbase = hkv * CR + 2 * half;
    float* P0 = g_part + (((size_t)(b * CH + rbase)) * NPART + slot) * PSTR;
    if (sub == 0) { P0[0] = st.m0; P0[1] = st.l0; }
    *(float4*)(P0 + 4 + sub * 8)     = st.a0a;
    *(float4*)(P0 + 4 + sub * 8 + 4) = st.a0b;
    float* P1 = g_part + (((size_t)(b * CH + rbase + 1)) * NPART + slot) * PSTR;
    if (sub == 0) { P1[0] = st.m1; P1[1] = st.l1; }
    *(float4*)(P1 + 4 + sub * 8)     = st.a1a;
    *(float4*)(P1 + 4 + sub * 8 + 4) = st.a1b;
}

__device__ __forceinline__ void hstate_init(HState& st) {
    st.m0 = st.m1 = -1e30f;
    st.l0 = st.l1 = 0.f;
    st.a0a = st.a0b = st.a1a = st.a1b = make_float4(0.f, 0.f, 0.f, 0.f);
}

// ---------------- 6) prefix attention over union pages -----------------------
__global__ void prefix_kernel(const float* __restrict__ ck, const float* __restrict__ cv) {
    int bid = blockIdx.x;
    int chunk = bid % PCH;
    int bh = bid / PCH;
    int hkv = bh % CHKV, b = bh / CHKV;
    int warp = threadIdx.x >> 5, lane = threadIdx.x & 31;
    int half = lane >> 4, sub = lane & 15;
    bool p = lane & 1;
    int cnt = g_ucnt[bh];
    const float* qb = g_q + (b * CH + hkv * CR + 2 * half) * CD + sub * 8;
    float4 q0a = *(const float4*)(qb);
    float4 q0b = *(const float4*)(qb + 4);
    float4 q1a = *(const float4*)(qb + CD);
    float4 q1b = *(const float4*)(qb + CD + 4);
    HState st;
    hstate_init(st);
    int e0 = chunk * 32 + warp * 4;
    for (int ei = e0; ei < e0 + 4 && ei < cnt; ei++) {
        int ent = g_uni[bh * 1024 + ei];
        int page = ent & 0xFFFF;
        int pm = ent >> 16;
        bool en0 = (pm >> (2 * half)) & 1;
        bool en1 = (pm >> (2 * half + 1)) & 1;
        size_t boff = (((size_t)b * CSTART + (size_t)page * CPAGE) * CHKV + hkv) * CD + sub * 8;
        const float* kp = ck + boff;
        const float* vp = cv + boff;
        for (int g = 0; g < 8; g++) {          // 16 keys, 2 per batch
            size_t o0 = (size_t)(2 * g) * (CHKV * CD);
            size_t o1 = (size_t)(2 * g + 1) * (CHKV * CD);
            float4 ka0 = *(const float4*)(kp + o0), kb0 = *(const float4*)(kp + o0 + 4);
            float4 va0 = *(const float4*)(vp + o0), vb0 = *(const float4*)(vp + o0 + 4);
            float4 ka1 = *(const float4*)(kp + o1), kb1 = *(const float4*)(kp + o1 + 4);
            float4 va1 = *(const float4*)(vp + o1), vb1 = *(const float4*)(vp + o1 + 4);
            key_step2(st, ka0, kb0, va0, vb0, q0a, q0b, q1a, q1b, p, en0, en1);
            key_step2(st, ka1, kb1, va1, vb1, q0a, q0b, q1a, q1b, p, en0, en1);
        }
    }
    write_partial2(st, b, hkv, half, sub, chunk * 8 + warp);
}

// ---------------- 7) suffix attention (window 4096 + new token) --------------
__global__ void suffix_kernel(const float* __restrict__ ck, const float* __restrict__ cv) {
    int bid = blockIdx.x;
    int chunk = bid % SCH;
    int bh = bid / SCH;
    int hkv = bh % CHKV, b = bh / CHKV;
    int warp = threadIdx.x >> 5, lane = threadIdx.x & 31;
    int half = lane >> 4, sub = lane & 15;
    bool p = lane & 1;
    const float* qb = g_q + (b * CH + hkv * CR + 2 * half) * CD + sub * 8;
    float4 q0a = *(const float4*)(qb);
    float4 q0b = *(const float4*)(qb + 4);
    float4 q1a = *(const float4*)(qb + CD);
    float4 q1b = *(const float4*)(qb + CD + 4);
    HState st;
    hstate_init(st);
    int key0 = chunk * 128 + warp * 16;
    size_t boff = (((size_t)b * CSTART + CPREF + key0) * CHKV + hkv) * CD + sub * 8;
    const float* kp = ck + boff;
    const float* vp = cv + boff;
    for (int g = 0; g < 8; g++) {
        size_t o0 = (size_t)(2 * g) * (CHKV * CD);
        size_t o1 = (size_t)(2 * g + 1) * (CHKV * CD);
        float4 ka0 = *(const float4*)(kp + o0), kb0 = *(const float4*)(kp + o0 + 4);
        float4 va0 = *(const float4*)(vp + o0), vb0 = *(const float4*)(vp + o0 + 4);
        float4 ka1 = *(const float4*)(kp + o1), kb1 = *(const float4*)(kp + o1 + 4);
        float4 va1 = *(const float4*)(vp + o1), vb1 = *(const float4*)(vp + o1 + 4);
        key_step2(st, ka0, kb0, va0, vb0, q0a, q0b, q1a, q1b, p, true, true);
        key_step2(st, ka1, kb1, va1, vb1, q0a, q0b, q1a, q1b, p, true, true);
    }
    if (chunk == SCH - 1 && warp == 7) {       // the just-computed token
        const float* knp = g_kn + (b * CHKV + hkv) * CD + sub * 8;
        const float* vnp = g_vn + (b * CHKV + hkv) * CD + sub * 8;
        float4 ka = *(const float4*)(knp), kb = *(const float4*)(knp + 4);
        float4 va = *(const float4*)(vnp), vb = *(const float4*)(vnp + 4);
        key_step2(st, ka, kb, va, vb, q0a, q0b, q1a, q1b, p, true, true);
    }
    write_partial2(st, b, hkv, half, sub, 256 + chunk * 8 + warp);
}

// ---------------- 8) merge all partials (exact logaddexp combine) ------------
__global__ void combine_kernel() {
    int bh = blockIdx.x;                       // b*H + h
    const float* P = g_part + (size_t)bh * NPART * PSTR;
    __shared__ float red[128];
    __shared__ float coef[NPART];
    int t = threadIdx.x;
    float mloc = -1e30f;
    for (int c = t; c < NPART; c += 128) mloc = fmaxf(mloc, P[(size_t)c * PSTR]);
    red[t] = mloc;
    for (int o = 64; o; o >>= 1) { __syncthreads(); if (t < o) red[t] = fmaxf(red[t], red[t + o]); }
    __syncthreads();
    float M = red[0];
    __syncthreads();
    float lloc = 0.f;
    for (int c = t; c < NPART; c += 128) {
        float w = __expf(P[(size_t)c * PSTR] - M);
        coef[c] = w;
        lloc += w * P[(size_t)c * PSTR + 1];
    }
    red[t] = lloc;
    for (int o = 64; o; o >>= 1) { __syncthreads(); if (t < o) red[t] += red[t + o]; }
    __syncthreads();
    float L = red[0];
    float o = 0.f;
    for (int c = 0; c < NPART; c++) o += coef[c] * P[(size_t)c * PSTR + 4 + t];
    int b = bh >> 5, h = bh & 31;
    g_attn[b * CDIM + h * CD + t] = o / L;
}

// ---------------- 9) output GEMV --------------------------------------------
__global__ void out_kernel(const float* __restrict__ wo, float* __restrict__ out) {
    __shared__ float sa0[CDIM], sa1[CDIM];
    for (int i = threadIdx.x; i < CDIM; i += 256) { sa0[i] = g_attn[i]; sa1[i] = g_attn[CDIM + i]; }
    __syncthreads();
    int warp = threadIdx.x >> 5, lane = threadIdx.x & 31;
    int row0 = (blockIdx.x * 8 + warp) * 4;
    for (int rr = 0; rr < 4; rr++) {
        int row = row0 + rr;
        const float* w = wo + (size_t)row * CDIM;
        float a0 = 0.f, a1 = 0.f;
        for (int j = lane * 4; j < CDIM; j += 128) {
            float4 wv4 = *(const float4*)(w + j);
            float4 x0 = *(const float4*)(sa0 + j);
            float4 x1 = *(const float4*)(sa1 + j);
            a0 += dot4(wv4, x0);
            a1 += dot4(wv4, x1);
        }
        for (int o = 16; o; o >>= 1) {
            a0 += __shfl_xor_sync(FULLMASK, a0, o);
            a1 += __shfl_xor_sync(FULLMASK, a1, o);
        }
        if (lane == 0) { out[row] = a0; out[CDIM + row] = a1; }
    }
}

// ---------------- launch ------------------------------------------------------
extern "C" void kernel_launch(void* const* d_in, const int* in_sizes, int n_in,
                              void* d_out, int out_size) {
    (void)in_sizes; (void)n_in; (void)out_size;
    const float* x    = (const float*)d_in[0];
    const float* fcos = (const float*)d_in[1];
    const float* fsin = (const float*)d_in[2];
    const float* ck   = (const float*)d_in[3];
    const float* cv   = (const float*)d_in[4];
    const float* wq   = (const float*)d_in[5];
    const float* wk   = (const float*)d_in[6];
    const float* wv   = (const float*)d_in[7];
    const float* wo   = (const float*)d_in[8];
    float* out = (float*)d_out;

    qkv_kernel<<<192, 256>>>(x, wq, wk, wv);
    rope_kernel<<<20, 256>>>(fcos, fsin);
    score_kernel<<<CB * CHKV * SCHUNKS, 256>>>(ck);
    topk_kernel<<<CB * CHKV * CR, 1024>>>();
    union_kernel<<<CB * CHKV, 256>>>();
    prefix_kernel<<<CB * CHKV * PCH, 256>>>(ck, cv);
    suffix_kernel<<<CB * CHKV * SCH, 256>>>(ck, cv);
    combine_kernel<<<CB * CH, 128>>>();
    out_kernel<<<128, 256>>>(wo, out);
}

// round 5
// speedup vs baseline: 1.1734x; 1.1203x over previous
#include <cuda_runtime.h>
#include <math.h>

#define FULLMASK 0xffffffffu
#define CB 2
#define CH 32
#define CHKV 8
#define CR 4
#define CD 128
#define CDIM 4096
#define CSTART 32768
#define CPREF 28672
#define CNPG 1792
#define CPAGE 16
#define CTOP 256
#define CSCALE 0.08838834764831845f

#define SCHUNKS 56   // scoring chunks per (b,hkv): 32 pages each
#define PCH 32       // prefix chunks per (b,hkv): 32 union entries each
#define SCH 32       // suffix chunks per (b,hkv): 128 keys each
#define NPART 512    // per head: 256 prefix warp-partials + 256 suffix
#define PSTR 132     // floats per partial: m, l, pad, pad, acc[128]

// ---------------- scratch (device globals; no allocation allowed) ------------
__device__ float g_q[CB * CH * CD];
__device__ float g_kn[CB * CHKV * CD];
__device__ float g_vn[CB * CHKV * CD];
__device__ float g_sc[CB * CNPG * CHKV * CR];        // [b][page][hkv][r]
__device__ int   g_top[CB * CHKV * CR * CTOP];
__device__ int   g_uni[CB * CHKV * 1024];            // page | mask<<16
__device__ int   g_ucnt[CB * CHKV];
__device__ float g_part[(size_t)CB * CH * NPART * PSTR];
__device__ float g_attn[CB * CDIM];

__device__ __forceinline__ float dot4(float4 a, float4 b) {
    return a.x * b.x + a.y * b.y + a.z * b.z + a.w * b.w;
}

// ---------------- 1) QKV GEMV (both batches share each weight row) -----------
__global__ void qkv_kernel(const float* __restrict__ x, const float* __restrict__ wq,
                           const float* __restrict__ wk, const float* __restrict__ wv) {
    __shared__ float sx0[CDIM], sx1[CDIM];
    for (int i = threadIdx.x; i < CDIM; i += 256) { sx0[i] = x[i]; sx1[i] = x[CDIM + i]; }
    __syncthreads();
    int warp = threadIdx.x >> 5, lane = threadIdx.x & 31;
    int row0 = (blockIdx.x * 8 + warp) * 2;
    for (int rr = 0; rr < 2; rr++) {
        int row = row0 + rr;           // 0..6143: [wq 4096 | wk 1024 | wv 1024]
        const float* w;
        if (row < 4096)      w = wq + (size_t)row * CDIM;
        else if (row < 5120) w = wk + (size_t)(row - 4096) * CDIM;
        else                 w = wv + (size_t)(row - 5120) * CDIM;
        float a0 = 0.f, a1 = 0.f;
        for (int j = lane * 4; j < CDIM; j += 128) {
            float4 wv4 = *(const float4*)(w + j);
            float4 x0 = *(const float4*)(sx0 + j);
            float4 x1 = *(const float4*)(sx1 + j);
            a0 += dot4(wv4, x0);
            a1 += dot4(wv4, x1);
        }
        for (int o = 16; o; o >>= 1) {
            a0 += __shfl_xor_sync(FULLMASK, a0, o);
            a1 += __shfl_xor_sync(FULLMASK, a1, o);
        }
        if (lane == 0) {
            if (row < 4096)      { g_q[row] = a0;  g_q[CDIM + row] = a1; }
            else if (row < 5120) { int i = row - 4096; g_kn[i] = a0; g_kn[CHKV * CD + i] = a1; }
            else                 { int i = row - 5120; g_vn[i] = a0; g_vn[CHKV * CD + i] = a1; }
        }
    }
}

// ---------------- 2) RoPE on q and new k (interleaved pairs) -----------------
__global__ void rope_kernel(const float* __restrict__ fc, const float* __restrict__ fs) {
    int idx = blockIdx.x * 256 + threadIdx.x;
    if (idx >= CB * (CH + CHKV) * (CD / 2)) return;
    int i = idx & 63;
    int rem = idx >> 6;               // b*(H+HKV) + hh
    int b = rem / (CH + CHKV);
    int hh = rem % (CH + CHKV);
    float c = fc[i], s = fs[i];
    float* base = (hh < CH) ? (g_q + (b * CH + hh) * CD)
                            : (g_kn + (b * CHKV + (hh - CH)) * CD);
    float t0 = base[2 * i], t1 = base[2 * i + 1];
    base[2 * i]     = t0 * c - t1 * s;
    base[2 * i + 1] = t0 * s + t1 * c;
}

// ---------------- 3) page scoring ---------------------------------------------
// Warp layout: half-warp h (lanes h*16..h*16+15) owns r-pair (2h, 2h+1).
// Lane owns 8 dims (sub = lane&15, dims sub*8..sub*8+8). Two-value butterfly
// over the 16 lanes: after shfl 1,2,4,8 lane holds full dot for r = 2h+(lane&1).
__global__ void score_kernel(const float* __restrict__ ck) {
    int bid = blockIdx.x;
    int chunk = bid % SCHUNKS;
    int bh = bid / SCHUNKS;
    int hkv = bh % CHKV, b = bh / CHKV;
    int warp = threadIdx.x >> 5, lane = threadIdx.x & 31;
    int half = lane >> 4, sub = lane & 15;
    bool p = lane & 1;
    const float* qb = g_q + (b * CH + hkv * CR + 2 * half) * CD + sub * 8;
    float4 q0a = *(const float4*)(qb);
    float4 q0b = *(const float4*)(qb + 4);
    float4 q1a = *(const float4*)(qb + CD);
    float4 q1b = *(const float4*)(qb + CD + 4);
    int page0 = chunk * 32 + warp * 4;
    for (int pp = 0; pp < 4; pp++) {
        int page = page0 + pp;
        const float* kp = ck + (((size_t)b * CSTART + (size_t)page * CPAGE) * CHKV + hkv) * CD + sub * 8;
        float mx = -1e30f;
        for (int g = 0; g < 8; g++) {  // 16 keys, 2 per batch
            float4 ka0 = *(const float4*)(kp + (size_t)(2 * g) * (CHKV * CD));
            float4 kb0 = *(const float4*)(kp + (size_t)(2 * g) * (CHKV * CD) + 4);
            float4 ka1 = *(const float4*)(kp + (size_t)(2 * g + 1) * (CHKV * CD));
            float4 kb1 = *(const float4*)(kp + (size_t)(2 * g + 1) * (CHKV * CD) + 4);
#pragma unroll
            for (int t = 0; t < 2; t++) {
                float4 ka = t ? ka1 : ka0, kb = t ? kb1 : kb0;
                float v0 = dot4(ka, q0a) + dot4(kb, q0b);
                float v1 = dot4(ka, q1a) + dot4(kb, q1b);
                float a = p ? v1 : v0, bb = p ? v0 : v1;
                a += __shfl_xor_sync(FULLMASK, bb, 1);
                a += __shfl_xor_sync(FULLMASK, a, 2);
                a += __shfl_xor_sync(FULLMASK, a, 4);
                a += __shfl_xor_sync(FULLMASK, a, 8);
                mx = fmaxf(mx, a);
            }
        }
        if ((lane & 14) == 0) {        // lanes 0,1,16,17 -> r = 2*half + p
            int r = 2 * half + (int)p;
            g_sc[((b * CNPG + page) * CHKV + hkv) * CR + r] = mx;
        }
    }
}

// ---------------- 4) top-256 pages per (b,hkv,r): bitonic, 1024 threads ------
// Stages with j<=16 have writer/reader groups warp-local (2j<=32 aligned
// threads) -> __syncwarp; only j>=32 stages need the full block barrier.
__global__ void topk_kernel() {
    __shared__ unsigned long long sk[2048];
    int inst = blockIdx.x;                    // b*32 + hkv*4 + r
    int r = inst & 3, hkv = (inst >> 2) & 7, b = inst >> 5;
    for (int i = threadIdx.x; i < 2048; i += 1024) {
        unsigned long long key;
        if (i < CNPG) {
            float f = g_sc[((b * CNPG + i) * CHKV + hkv) * CR + r];
            unsigned u = __float_as_uint(f);
            unsigned su = (u >> 31) ? ~u : (u | 0x80000000u);  // ascending-orderable
            unsigned du = ~su;                                  // ascending du == descending f
            key = (((unsigned long long)du) << 32) | (unsigned)i;
        } else {
            key = 0xFFFFFFFFFFFFFFFFull;
        }
        sk[i] = key;
    }
    __syncthreads();
    int t = threadIdx.x;                      // one compare per thread per stage
    for (int k = 2; k <= 2048; k <<= 1) {
        for (int j = k >> 1; j; j >>= 1) {
            int i = ((t & ~(j - 1)) << 1) | (t & (j - 1));
            int ixj = i | j;
            unsigned long long A = sk[i], Bv = sk[ixj];
            bool desc = (i & k) != 0;
            if ((A > Bv) != desc) { sk[i] = Bv; sk[ixj] = A; }
            if (j > 32) __syncthreads();
            else __syncwarp();
        }
        // between k-groups the first stage has j=k/2; barrier choice above for
        // the last j=1 stage was syncwarp; the next read (j=k) spans wide:
        if (k < 2048 && k >= 32) __syncthreads();
    }
    __syncthreads();
    if (t < CTOP)
        g_top[inst * CTOP + t] = (int)(sk[t] & 0xFFFFFFFFu);
}

// ---------------- 5) union of pages across 4 reps + mask, deterministic -----
__global__ void union_kernel() {
    __shared__ int mask[CNPG];
    __shared__ int wtot[8];
    int bh = blockIdx.x;                      // b*HKV + hkv
    int warp = threadIdx.x >> 5, lane = threadIdx.x & 31;
    for (int i = threadIdx.x; i < CNPG; i += 256) mask[i] = 0;
    __syncthreads();
    for (int r = 0; r < CR; r++) {
        int i = threadIdx.x;
        if (i < CTOP) {
            int p = g_top[(bh * CR + r) * CTOP + i];
            atomicOr(&mask[p], 1 << r);
        }
    }
    __syncthreads();
    int base = threadIdx.x * 7;               // 256*7 = 1792
    int cnt = 0;
    for (int j = 0; j < 7; j++) if (mask[base + j]) cnt++;
    int v = cnt;
    for (int o = 1; o < 32; o <<= 1) {
        int u = __shfl_up_sync(FULLMASK, v, o);
        if (lane >= o) v += u;
    }
    if (lane == 31) wtot[warp] = v;
    __syncthreads();
    if (threadIdx.x == 0) {
        int s = 0;
        for (int i = 0; i < 8; i++) { int t = wtot[i]; wtot[i] = s; s += t; }
        g_ucnt[bh] = (s > 1024) ? 1024 : s;
    }
    __syncthreads();
    int off = v - cnt + wtot[warp];
    for (int j = 0; j < 7; j++) {
        int p = base + j;
        int mk = mask[p];
        if (mk && off < 1024) g_uni[bh * 1024 + off++] = p | (mk << 16);
    }
}

// ---------------- flash inner step (half-warp r-pair layout) -----------------
#define UPD2(MM, LL, ACA, ACB, SV)                                                   \
    do {                                                                             \
        if ((SV) > (MM)) {                                                           \
            float cr_ = __expf((MM) - (SV));                                         \
            MM = (SV); LL *= cr_;                                                    \
            ACA.x *= cr_; ACA.y *= cr_; ACA.z *= cr_; ACA.w *= cr_;                  \
            ACB.x *= cr_; ACB.y *= cr_; ACB.z *= cr_; ACB.w *= cr_;                  \
        }                                                                            \
        float e_ = __expf((SV) - (MM));                                              \
        LL += e_;                                                                    \
        ACA.x += e_ * va.x; ACA.y += e_ * va.y; ACA.z += e_ * va.z; ACA.w += e_ * va.w; \
        ACB.x += e_ * vb.x; ACB.y += e_ * vb.y; ACB.z += e_ * vb.z; ACB.w += e_ * vb.w; \
    } while (0)

struct HState {
    float m0, l0, m1, l1;
    float4 a0a, a0b, a1a, a1b;
};

__device__ __forceinline__ void key_step2(HState& st, float4 ka, float4 kb,
                                          float4 va, float4 vb,
                                          float4 q0a, float4 q0b, float4 q1a, float4 q1b,
                                          bool p, bool en0, bool en1) {
    float v0 = dot4(ka, q0a) + dot4(kb, q0b);
    float v1 = dot4(ka, q1a) + dot4(kb, q1b);
    float a = p ? v1 : v0, bb = p ? v0 : v1;
    a += __shfl_xor_sync(FULLMASK, bb, 1);
    a += __shfl_xor_sync(FULLMASK, a, 2);
    a += __shfl_xor_sync(FULLMASK, a, 4);
    a += __shfl_xor_sync(FULLMASK, a, 8);
    a *= CSCALE;                               // lane holds s for r = 2h+(lane&1)
    float so = __shfl_xor_sync(FULLMASK, a, 1);
    float sA = p ? so : a;                     // r = 2h
    float sB = p ? a : so;                     // r = 2h+1
    if (en0) UPD2(st.m0, st.l0, st.a0a, st.a0b, sA);
    if (en1) UPD2(st.m1, st.l1, st.a1a, st.a1b, sB);
}

__device__ __forceinline__ void write_partial2(const HState& st, int b, int hkv,
                                               int half, int sub, int slot) {
    int rbase = hkv * CR + 2 * half;
    float* P0 = g_part + (((size_t)(b * CH + rbase)) * NPART + slot) * PSTR;
    if (sub == 0) { P0[0] = st.m0; P0[1] = st.l0; }
    *(float4*)(P0 + 4 + sub * 8)     = st.a0a;
    *(float4*)(P0 + 4 + sub * 8 + 4) = st.a0b;
    float* P1 = g_part + (((size_t)(b * CH + rbase + 1)) * NPART + slot) * PSTR;
    if (sub == 0) { P1[0] = st.m1; P1[1] = st.l1; }
    *(float4*)(P1 + 4 + sub * 8)     = st.a1a;
    *(float4*)(P1 + 4 + sub * 8 + 4) = st.a1b;
}

__device__ __forceinline__ void hstate_init(HState& st) {
    st.m0 = st.m1 = -1e30f;
    st.l0 = st.l1 = 0.f;
    st.a0a = st.a0b = st.a1a = st.a1b = make_float4(0.f, 0.f, 0.f, 0.f);
}

// ---------------- 6) prefix attention over union pages -----------------------
__global__ void prefix_kernel(const float* __restrict__ ck, const float* __restrict__ cv) {
    int bid = blockIdx.x;
    int chunk = bid % PCH;
    int bh = bid / PCH;
    int hkv = bh % CHKV, b = bh / CHKV;
    int warp = threadIdx.x >> 5, lane = threadIdx.x & 31;
    int half = lane >> 4, sub = lane & 15;
    bool p = lane & 1;
    int cnt = g_ucnt[bh];
    const float* qb = g_q + (b * CH + hkv * CR + 2 * half) * CD + sub * 8;
    float4 q0a = *(const float4*)(qb);
    float4 q0b = *(const float4*)(qb + 4);
    float4 q1a = *(const float4*)(qb + CD);
    float4 q1b = *(const float4*)(qb + CD + 4);
    HState st;
    hstate_init(st);
    int e0 = chunk * 32 + warp * 4;
    for (int ei = e0; ei < e0 + 4 && ei < cnt; ei++) {
        int ent = g_uni[bh * 1024 + ei];
        int page = ent & 0xFFFF;
        int pm = ent >> 16;
        bool en0 = (pm >> (2 * half)) & 1;
        bool en1 = (pm >> (2 * half + 1)) & 1;
        size_t boff = (((size_t)b * CSTART + (size_t)page * CPAGE) * CHKV + hkv) * CD + sub * 8;
        const float* kp = ck + boff;
        const float* vp = cv + boff;
        for (int g = 0; g < 8; g++) {          // 16 keys, 2 per batch
            size_t o0 = (size_t)(2 * g) * (CHKV * CD);
            size_t o1 = (size_t)(2 * g + 1) * (CHKV * CD);
            float4 ka0 = *(const float4*)(kp + o0), kb0 = *(const float4*)(kp + o0 + 4);
            float4 va0 = *(const float4*)(vp + o0), vb0 = *(const float4*)(vp + o0 + 4);
            float4 ka1 = *(const float4*)(kp + o1), kb1 = *(const float4*)(kp + o1 + 4);
            float4 va1 = *(const float4*)(vp + o1), vb1 = *(const float4*)(vp + o1 + 4);
            key_step2(st, ka0, kb0, va0, vb0, q0a, q0b, q1a, q1b, p, en0, en1);
            key_step2(st, ka1, kb1, va1, vb1, q0a, q0b, q1a, q1b, p, en0, en1);
        }
    }
    write_partial2(st, b, hkv, half, sub, chunk * 8 + warp);
}

// ---------------- 7) suffix attention (window 4096 + new token) --------------
__global__ void suffix_kernel(const float* __restrict__ ck, const float* __restrict__ cv) {
    int bid = blockIdx.x;
    int chunk = bid % SCH;
    int bh = bid / SCH;
    int hkv = bh % CHKV, b = bh / CHKV;
    int warp = threadIdx.x >> 5, lane = threadIdx.x & 31;
    int half = lane >> 4, sub = lane & 15;
    bool p = lane & 1;
    const float* qb = g_q + (b * CH + hkv * CR + 2 * half) * CD + sub * 8;
    float4 q0a = *(const float4*)(qb);
    float4 q0b = *(const float4*)(qb + 4);
    float4 q1a = *(const float4*)(qb + CD);
    float4 q1b = *(const float4*)(qb + CD + 4);
    HState st;
    hstate_init(st);
    int key0 = chunk * 128 + warp * 16;
    size_t boff = (((size_t)b * CSTART + CPREF + key0) * CHKV + hkv) * CD + sub * 8;
    const float* kp = ck + boff;
    const float* vp = cv + boff;
    for (int g = 0; g < 8; g++) {
        size_t o0 = (size_t)(2 * g) * (CHKV * CD);
        size_t o1 = (size_t)(2 * g + 1) * (CHKV * CD);
        float4 ka0 = *(const float4*)(kp + o0), kb0 = *(const float4*)(kp + o0 + 4);
        float4 va0 = *(const float4*)(vp + o0), vb0 = *(const float4*)(vp + o0 + 4);
        float4 ka1 = *(const float4*)(kp + o1), kb1 = *(const float4*)(kp + o1 + 4);
        float4 va1 = *(const float4*)(vp + o1), vb1 = *(const float4*)(vp + o1 + 4);
        key_step2(st, ka0, kb0, va0, vb0, q0a, q0b, q1a, q1b, p, true, true);
        key_step2(st, ka1, kb1, va1, vb1, q0a, q0b, q1a, q1b, p, true, true);
    }
    if (chunk == SCH - 1 && warp == 7) {       // the just-computed token
        const float* knp = g_kn + (b * CHKV + hkv) * CD + sub * 8;
        const float* vnp = g_vn + (b * CHKV + hkv) * CD + sub * 8;
        float4 ka = *(const float4*)(knp), kb = *(const float4*)(knp + 4);
        float4 va = *(const float4*)(vnp), vb = *(const float4*)(vnp + 4);
        key_step2(st, ka, kb, va, vb, q0a, q0b, q1a, q1b, p, true, true);
    }
    write_partial2(st, b, hkv, half, sub, 256 + chunk * 8 + warp);
}

// ---------------- 8) merge all partials (exact logaddexp combine) ------------
__global__ void combine_kernel() {
    int bh = blockIdx.x;                       // b*H + h
    const float* P = g_part + (size_t)bh * NPART * PSTR;
    __shared__ float red[128];
    __shared__ float coef[NPART];
    int t = threadIdx.x;
    float mloc = -1e30f;
    for (int c = t; c < NPART; c += 128) mloc = fmaxf(mloc, P[(size_t)c * PSTR]);
    red[t] = mloc;
    for (int o = 64; o; o >>= 1) { __syncthreads(); if (t < o) red[t] = fmaxf(red[t], red[t + o]); }
    __syncthreads();
    float M = red[0];
    __syncthreads();
    float lloc = 0.f;
    for (int c = t; c < NPART; c += 128) {
        float w = __expf(P[(size_t)c * PSTR] - M);
        coef[c] = w;
        lloc += w * P[(size_t)c * PSTR + 1];
    }
    red[t] = lloc;
    for (int o = 64; o; o >>= 1) { __syncthreads(); if (t < o) red[t] += red[t + o]; }
    __syncthreads();
    float L = red[0];
    float o = 0.f;
    for (int c = 0; c < NPART; c++) o += coef[c] * P[(size_t)c * PSTR + 4 + t];
    int b = bh >> 5, h = bh & 31;
    g_attn[b * CDIM + h * CD + t] = o / L;
}

// ---------------- 9) output GEMV --------------------------------------------
__global__ void out_kernel(const float* __restrict__ wo, float* __restrict__ out) {
    __shared__ float sa0[CDIM], sa1[CDIM];
    for (int i = threadIdx.x; i < CDIM; i += 256) { sa0[i] = g_attn[i]; sa1[i] = g_attn[CDIM + i]; }
    __syncthreads();
    int warp = threadIdx.x >> 5, lane = threadIdx.x & 31;
    int row0 = (blockIdx.x * 8 + warp) * 4;
    for (int rr = 0; rr < 4; rr++) {
        int row = row0 + rr;
        const float* w = wo + (size_t)row * CDIM;
        float a0 = 0.f, a1 = 0.f;
        for (int j = lane * 4; j < CDIM; j += 128) {
            float4 wv4 = *(const float4*)(w + j);
            float4 x0 = *(const float4*)(sa0 + j);
            float4 x1 = *(const float4*)(sa1 + j);
            a0 += dot4(wv4, x0);
            a1 += dot4(wv4, x1);
        }
        for (int o = 16; o; o >>= 1) {
            a0 += __shfl_xor_sync(FULLMASK, a0, o);
            a1 += __shfl_xor_sync(FULLMASK, a1, o);
        }
        if (lane == 0) { out[row] = a0; out[CDIM + row] = a1; }
    }
}

// ---------------- streams/events for fork-join (created once, host-side) -----
struct SideStream {
    cudaStream_t s2;
    cudaEvent_t e_fork, e_join;
    SideStream() {
        cudaStreamCreateWithFlags(&s2, cudaStreamNonBlocking);
        cudaEventCreateWithFlags(&e_fork, cudaEventDisableTiming);
        cudaEventCreateWithFlags(&e_join, cudaEventDisableTiming);
    }
};
static SideStream g_ss;

// ---------------- launch ------------------------------------------------------
extern "C" void kernel_launch(void* const* d_in, const int* in_sizes, int n_in,
                              void* d_out, int out_size) {
    (void)in_sizes; (void)n_in; (void)out_size;
    const float* x    = (const float*)d_in[0];
    const float* fcos = (const float*)d_in[1];
    const float* fsin = (const float*)d_in[2];
    const float* ck   = (const float*)d_in[3];
    const float* cv   = (const float*)d_in[4];
    const float* wq   = (const float*)d_in[5];
    const float* wk   = (const float*)d_in[6];
    const float* wv   = (const float*)d_in[7];
    const float* wo   = (const float*)d_in[8];
    float* out = (float*)d_out;

    qkv_kernel<<<384, 256>>>(x, wq, wk, wv);
    rope_kernel<<<20, 256>>>(fcos, fsin);

    // fork: suffix depends only on q/kn/vn; run it alongside the scoring chain
    cudaEventRecord(g_ss.e_fork, 0);
    cudaStreamWaitEvent(g_ss.s2, g_ss.e_fork, 0);
    suffix_kernel<<<CB * CHKV * SCH, 256, 0, g_ss.s2>>>(ck, cv);
    cudaEventRecord(g_ss.e_join, g_ss.s2);

    score_kernel<<<CB * CHKV * SCHUNKS, 256>>>(ck);
    topk_kernel<<<CB * CHKV * CR, 1024>>>();
    union_kernel<<<CB * CHKV, 256>>>();
    prefix_kernel<<<CB * CHKV * PCH, 256>>>(ck, cv);

    // join before combine
    cudaStreamWaitEvent(0, g_ss.e_join, 0);
    combine_kernel<<<CB * CH, 128>>>();
    out_kernel<<<128, 256>>>(wo, out);
}